// round 1
// baseline (speedup 1.0000x reference)
#include <cuda_runtime.h>
#include <math.h>

#define EPSV 0.001f
#define KMIX 8
#define LOG2E 1.4426950408889634f

// Precomputed per-component parameters (filled by setup kernel).
__device__ float g_mu[KMIX];
__device__ float g_a2[KMIX];   // -0.5*log2(e)/v^2          (denom exponent, base-2)
__device__ float g_b2[KMIX];   // -0.5*log2(e)/(v+EPS)^2    (numer exponent, base-2)
__device__ float g_pr[KMIX];   // softmax(prior)
__device__ float g_w[KMIX];    // pr / (sqrt(pr+EPS)*sqrt(v+EPS))

__device__ __forceinline__ float ex2f(float x) {
    float y;
    asm("ex2.approx.ftz.f32 %0, %1;" : "=f"(y) : "f"(x));
    return y;
}
__device__ __forceinline__ float rcpf(float x) {
    float y;
    asm("rcp.approx.ftz.f32 %0, %1;" : "=f"(y) : "f"(x));
    return y;
}

// One-thread setup: softplus(variance), softmax(prior), fold constants.
__global__ void acn_setup_kernel(const float* __restrict__ mean,
                                 const float* __restrict__ variance,
                                 const float* __restrict__ prior) {
    if (threadIdx.x != 0 || blockIdx.x != 0) return;
    float v[KMIX], p[KMIX];
    float pmax = -1e30f;
    for (int k = 0; k < KMIX; k++) {
        v[k] = log1pf(expf(variance[k]));   // softplus
        p[k] = prior[k];
        pmax = fmaxf(pmax, p[k]);
    }
    float psum = 0.f;
    for (int k = 0; k < KMIX; k++) {
        p[k] = expf(p[k] - pmax);
        psum += p[k];
    }
    float inv = 1.f / psum;
    for (int k = 0; k < KMIX; k++) {
        float pr = p[k] * inv;
        float vk = v[k];
        float ve = vk + EPSV;
        g_mu[k] = mean[k];
        g_a2[k] = -0.5f * LOG2E / (vk * vk);
        g_b2[k] = -0.5f * LOG2E / (ve * ve);
        g_pr[k] = pr;
        g_w[k]  = pr / (sqrtf(pr + EPSV) * sqrtf(ve));
    }
}

__global__ void __launch_bounds__(256)
acn_main_kernel(const float4* __restrict__ x4, float4* __restrict__ o4,
                int n4, const float* __restrict__ x_tail,
                float* __restrict__ o_tail, int ntail) {
    // Load per-k params once per thread (amortized over many float4s; L2-hit LDGs).
    float mu[KMIX], a2[KMIX], b2[KMIX], pr[KMIX], w[KMIX];
#pragma unroll
    for (int k = 0; k < KMIX; k++) {
        mu[k] = g_mu[k]; a2[k] = g_a2[k]; b2[k] = g_b2[k];
        pr[k] = g_pr[k]; w[k]  = g_w[k];
    }

    const int stride = gridDim.x * blockDim.x;
    for (int i = blockIdx.x * blockDim.x + threadIdx.x; i < n4; i += stride) {
        float4 xv = x4[i];
        float xs[4] = {xv.x, xv.y, xv.z, xv.w};
        float S[4] = {0.f, 0.f, 0.f, 0.f};
        float D[4] = {0.f, 0.f, 0.f, 0.f};
#pragma unroll
        for (int k = 0; k < KMIX; k++) {
#pragma unroll
            for (int j = 0; j < 4; j++) {
                float d  = xs[j] - mu[k];
                float d2 = d * d;
                float e1 = ex2f(a2[k] * d2);
                float e2 = ex2f(b2[k] * d2);
                D[j] = fmaf(pr[k], e1, D[j]);
                S[j] = fmaf(w[k] * d, e2, S[j]);
            }
        }
        float4 ov;
        ov.x = S[0] * rcpf(D[0] + EPSV);
        ov.y = S[1] * rcpf(D[1] + EPSV);
        ov.z = S[2] * rcpf(D[2] + EPSV);
        ov.w = S[3] * rcpf(D[3] + EPSV);
        o4[i] = ov;
    }

    // Scalar tail (dead for this shape; kept for safety).
    if (blockIdx.x == 0 && (int)threadIdx.x < ntail) {
        int idx = (int)threadIdx.x;
        float xx = x_tail[idx];
        float S = 0.f, D = 0.f;
#pragma unroll
        for (int k = 0; k < KMIX; k++) {
            float d  = xx - mu[k];
            float d2 = d * d;
            D = fmaf(pr[k], ex2f(a2[k] * d2), D);
            S = fmaf(w[k] * d, ex2f(b2[k] * d2), S);
        }
        o_tail[idx] = S * rcpf(D + EPSV);
    }
}

extern "C" void kernel_launch(void* const* d_in, const int* in_sizes, int n_in,
                              void* d_out, int out_size) {
    const float* x        = (const float*)d_in[0];
    const float* mean     = (const float*)d_in[1];
    const float* variance = (const float*)d_in[2];
    const float* prior    = (const float*)d_in[3];
    float* out = (float*)d_out;

    int n    = in_sizes[0];
    int n4   = n >> 2;
    int ntail = n & 3;

    acn_setup_kernel<<<1, 1>>>(mean, variance, prior);

    int threads = 256;
    int blocks  = 2048;  // grid-stride; ~8 float4 per thread at this shape
    acn_main_kernel<<<blocks, threads>>>(
        (const float4*)x, (float4*)out, n4,
        x + (n - ntail), out + (n - ntail), ntail);
}

// round 2
// speedup vs baseline: 1.0761x; 1.0761x over previous
#include <cuda_runtime.h>
#include <math.h>

#define EPSV 0.001f
#define KMIX 8
#define LOG2E 1.4426950408889634f
#define LN2   0.6931471805599453f
#define LN2SQ_HALF 0.2402265069591007f

typedef unsigned long long ull;

// ---------- packed f32x2 helpers (sm_100+/sm_103a) ----------
__device__ __forceinline__ ull pk2(float lo, float hi) {
    ull r; asm("mov.b64 %0, {%1, %2};" : "=l"(r) : "f"(lo), "f"(hi)); return r;
}
__device__ __forceinline__ void unpk2(float& lo, float& hi, ull v) {
    asm("mov.b64 {%0, %1}, %2;" : "=f"(lo), "=f"(hi) : "l"(v));
}
__device__ __forceinline__ ull add2(ull a, ull b) {
    ull r; asm("add.rn.f32x2 %0, %1, %2;" : "=l"(r) : "l"(a), "l"(b)); return r;
}
__device__ __forceinline__ ull mul2(ull a, ull b) {
    ull r; asm("mul.rn.f32x2 %0, %1, %2;" : "=l"(r) : "l"(a), "l"(b)); return r;
}
__device__ __forceinline__ ull fma2(ull a, ull b, ull c) {
    ull r; asm("fma.rn.f32x2 %0, %1, %2, %3;" : "=l"(r) : "l"(a), "l"(b), "l"(c)); return r;
}
__device__ __forceinline__ float ex2f(float x) {
    float y; asm("ex2.approx.ftz.f32 %0, %1;" : "=f"(y) : "f"(x)); return y;
}
__device__ __forceinline__ float rcpf(float x) {
    float y; asm("rcp.approx.ftz.f32 %0, %1;" : "=f"(y) : "f"(x)); return y;
}

__global__ void __launch_bounds__(256)
acn_fused_kernel(const float4* __restrict__ x4, float4* __restrict__ o4, int n4,
                 const float* __restrict__ mean,
                 const float* __restrict__ variance,
                 const float* __restrict__ prior,
                 const float* __restrict__ x_tail,
                 float* __restrict__ o_tail, int ntail) {
    // --- per-block parameter setup (thread 0 -> smem) ---
    __shared__ float s_nmu[KMIX], s_a2[KMIX], s_cb[KMIX], s_pr[KMIX], s_w[KMIX];
    if (threadIdx.x == 0) {
        float v[KMIX], p[KMIX];
        float pmax = -1e30f;
        for (int k = 0; k < KMIX; k++) {
            v[k] = log1pf(expf(variance[k]));      // softplus
            p[k] = prior[k];
            pmax = fmaxf(pmax, p[k]);
        }
        float psum = 0.f;
        for (int k = 0; k < KMIX; k++) { p[k] = expf(p[k] - pmax); psum += p[k]; }
        float inv = 1.f / psum;
        for (int k = 0; k < KMIX; k++) {
            float pr = p[k] * inv;
            float vk = v[k];
            float ve = vk + EPSV;
            float a2 = -0.5f * LOG2E / (vk * vk);       // denom exponent (base 2)
            float b2 = -0.5f * LOG2E / (ve * ve);       // numer exponent (base 2)
            s_nmu[k] = -mean[k];
            s_a2[k]  = a2;
            s_cb[k]  = b2 - a2;                          // small positive delta
            s_pr[k]  = pr;
            s_w[k]   = pr / (sqrtf(pr + EPSV) * sqrtf(ve));
        }
    }
    __syncthreads();

    // --- broadcast params into packed registers ---
    ull P_nmu[KMIX], P_a2[KMIX], P_cb[KMIX], P_pr[KMIX], P_w[KMIX];
#pragma unroll
    for (int k = 0; k < KMIX; k++) {
        P_nmu[k] = pk2(s_nmu[k], s_nmu[k]);
        P_a2[k]  = pk2(s_a2[k],  s_a2[k]);
        P_cb[k]  = pk2(s_cb[k],  s_cb[k]);
        P_pr[k]  = pk2(s_pr[k],  s_pr[k]);
        P_w[k]   = pk2(s_w[k],   s_w[k]);
    }
    const ull C1P  = pk2(LN2, LN2);
    const ull C2P  = pk2(LN2SQ_HALF, LN2SQ_HALF);
    const ull ONE2 = pk2(1.0f, 1.0f);
    const ull EPS2 = pk2(EPSV, EPSV);

    const int stride = gridDim.x * blockDim.x;
    for (int i = blockIdx.x * blockDim.x + threadIdx.x; i < n4; i += stride) {
        float4 xv = x4[i];
        ull x01 = pk2(xv.x, xv.y);
        ull x23 = pk2(xv.z, xv.w);
        ull S01 = 0ull, S23 = 0ull, D01 = 0ull, D23 = 0ull;

#pragma unroll
        for (int k = 0; k < KMIX; k++) {
            ull d01 = add2(x01, P_nmu[k]);
            ull d23 = add2(x23, P_nmu[k]);
            ull q01 = mul2(d01, d01);               // d^2
            ull q23 = mul2(d23, d23);
            ull t01 = mul2(P_a2[k], q01);           // base-2 exponent for e1
            ull t23 = mul2(P_a2[k], q23);
            ull u01 = mul2(P_cb[k], q01);           // small base-2 delta
            ull u23 = mul2(P_cb[k], q23);

            float ta, tb, tc, td;
            unpk2(ta, tb, t01);
            unpk2(tc, td, t23);
            ull E01 = pk2(ex2f(ta), ex2f(tb));      // e1 = 2^(a*d^2)
            ull E23 = pk2(ex2f(tc), ex2f(td));

            // p = 1 + ln2*u + (ln2^2/2)*u^2  ~= 2^u   (u in [0, ~0.19])
            ull p01 = fma2(C2P, u01, C1P); p01 = fma2(p01, u01, ONE2);
            ull p23 = fma2(C2P, u23, C1P); p23 = fma2(p23, u23, ONE2);

            ull wd01 = mul2(P_w[k], d01);
            ull wd23 = mul2(P_w[k], d23);

            D01 = fma2(P_pr[k], E01, D01);          // denom += pr * e1
            D23 = fma2(P_pr[k], E23, D23);

            ull g01 = mul2(wd01, E01);              // w*d*e1
            ull g23 = mul2(wd23, E23);
            S01 = fma2(g01, p01, S01);              // S += w*d*e1*2^u  (= w*d*e2)
            S23 = fma2(g23, p23, S23);
        }

        ull Dp01 = add2(D01, EPS2);
        ull Dp23 = add2(D23, EPS2);
        float d0, d1, d2, d3, s0, s1, s2, s3;
        unpk2(d0, d1, Dp01); unpk2(d2, d3, Dp23);
        unpk2(s0, s1, S01);  unpk2(s2, s3, S23);
        float4 ov;
        ov.x = s0 * rcpf(d0);
        ov.y = s1 * rcpf(d1);
        ov.z = s2 * rcpf(d2);
        ov.w = s3 * rcpf(d3);
        o4[i] = ov;
    }

    // Scalar tail (dead for this shape; kept for safety).
    if (blockIdx.x == 0 && (int)threadIdx.x < ntail) {
        int idx = (int)threadIdx.x;
        float xx = x_tail[idx];
        float S = 0.f, D = 0.f;
#pragma unroll
        for (int k = 0; k < KMIX; k++) {
            float d  = xx + s_nmu[k];
            float dd = d * d;
            float e1 = ex2f(s_a2[k] * dd);
            float u  = s_cb[k] * dd;
            float p  = fmaf(fmaf(LN2SQ_HALF, u, LN2), u, 1.0f);
            D = fmaf(s_pr[k], e1, D);
            S = fmaf(s_w[k] * d * e1, p, S);
        }
        o_tail[idx] = S * rcpf(D + EPSV);
    }
}

extern "C" void kernel_launch(void* const* d_in, const int* in_sizes, int n_in,
                              void* d_out, int out_size) {
    const float* x        = (const float*)d_in[0];
    const float* mean     = (const float*)d_in[1];
    const float* variance = (const float*)d_in[2];
    const float* prior    = (const float*)d_in[3];
    float* out = (float*)d_out;

    int n     = in_sizes[0];
    int n4    = n >> 2;
    int ntail = n & 3;

    acn_fused_kernel<<<2048, 256>>>(
        (const float4*)x, (float4*)out, n4,
        mean, variance, prior,
        x + (n - ntail), out + (n - ntail), ntail);
}